// round 11
// baseline (speedup 1.0000x reference)
#include <cuda_runtime.h>
#include <cuda_bf16.h>
#include <cstdint>

#define B_SZ 1024
#define C_SZ 128
#define ELL 16
#define EQ 3
#define E_SZ 10
#define P3 23
#define P2 5
#define OUT_STRIDE 384
#define MROWS 48          // (w,xx) rows, m = w*16 + xx
#define KSYM 136          // symmetrized (v<=i) pairs
#define KTOT 160          // 136 + 16 + 1, padded
#define KPAIR 80          // KTOT/2 bf16 pairs
#define KW 29             // 23 + 5 + 1 weight slots
#define NT 16             // b-tile
#define GSZ (MROWS * KTOT)  // 7680
#define LDA 84            // smem pair-stride (conflict-free: 84 % 32 == 20)

__device__ int g_order[B_SZ];
__device__ int g_bstart[E_SZ + 1];
__device__ __align__(16) float g_AbigT[KW * GSZ];                 // [kp][o]
__device__ __align__(16) __nv_bfloat16 g_Ghi[E_SZ * C_SZ * GSZ];
__device__ __align__(16) __nv_bfloat16 g_Glo[E_SZ * C_SZ * GSZ];

// ---- packed f32x2 helpers ----
static __device__ __forceinline__ unsigned long long pack2(float lo, float hi) {
    unsigned long long r;
    asm("mov.b64 %0, {%1, %2};" : "=l"(r) : "f"(lo), "f"(hi));
    return r;
}
static __device__ __forceinline__ void unpack2(float& lo, float& hi, unsigned long long v) {
    asm("mov.b64 {%0, %1}, %2;" : "=f"(lo), "=f"(hi) : "l"(v));
}
static __device__ __forceinline__ unsigned long long fma2(unsigned long long a,
                                                          unsigned long long b,
                                                          unsigned long long c) {
    unsigned long long d;
    asm("fma.rn.f32x2 %0, %1, %2, %3;" : "=l"(d) : "l"(a), "l"(b), "l"(c));
    return d;
}

// ---------------------------------------------------------------------------
// Kernel A: bucket batch indices by element (y is exact one-hot).
// ---------------------------------------------------------------------------
__global__ void bucket_kernel(const float* __restrict__ y) {
    __shared__ int cnt[E_SZ];
    __shared__ int pfx[E_SZ + 1];
    int b = threadIdx.x;
    if (b < E_SZ) cnt[b] = 0;
    __syncthreads();
    int e = 0;
#pragma unroll
    for (int j = 1; j < E_SZ; j++)
        if (y[b * E_SZ + j] > 0.5f) e = j;
    int idx = atomicAdd(&cnt[e], 1);
    __syncthreads();
    if (b == 0) {
        int s = 0;
        for (int j = 0; j < E_SZ; j++) { pfx[j] = s; s += cnt[j]; }
        pfx[E_SZ] = s;
    }
    __syncthreads();
    g_order[pfx[e] + idx] = b;
    if (b <= E_SZ) g_bstart[b] = pfx[b];
}

// ---------------------------------------------------------------------------
// Kernel B1: AbigT[kp][m*160+k] — element-independent coefficient matrix.
// ---------------------------------------------------------------------------
__global__ void build_abig_kernel(const float* __restrict__ U3,
                                  const float* __restrict__ U2,
                                  const float* __restrict__ U1) {
    int o = blockIdx.x * 256 + threadIdx.x;
    if (o >= GSZ) return;
    int m = o / KTOT, k = o % KTOT;
    float vals[KW];
#pragma unroll
    for (int j = 0; j < KW; j++) vals[j] = 0.f;
    if (k < KSYM) {
        int kk = k, v = 0;
        while (kk >= ELL - v) { kk -= ELL - v; v++; }
        int i = v + kk;
        const float* p1 = U3 + ((size_t)(m * ELL + v) * ELL + i) * P3;
        const float* p2 = U3 + ((size_t)(m * ELL + i) * ELL + v) * P3;
#pragma unroll
        for (int kp = 0; kp < P3; kp++)
            vals[kp] = p1[kp] + (v != i ? p2[kp] : 0.f);
    } else if (k < KSYM + ELL) {
        int v = k - KSYM;
#pragma unroll
        for (int k2 = 0; k2 < P2; k2++)
            vals[P3 + k2] = U2[(m * ELL + v) * P2 + k2];
    } else if (k == KSYM + ELL) {
        vals[P3 + P2] = U1[m];
    }
#pragma unroll
    for (int j = 0; j < KW; j++)
        g_AbigT[j * GSZ + o] = vals[j];
}

// ---------------------------------------------------------------------------
// Kernel B2: G[ec, o] = sum_kp AbigT[kp, o] * W[ec, kp]; bf16 hi/lo split.
// Grid (30, 16): bx = o-tile of 256, by = ec-tile of 80.
// fma.rn.f32x2 over ec-pairs; ws transposed so pairs are LDS.64 broadcasts.
// ---------------------------------------------------------------------------
__global__ void __launch_bounds__(256) build_g_kernel(
    const float* __restrict__ wmax, const float* __restrict__ w2,
    const float* __restrict__ w1) {
    int o = blockIdx.x * 256 + threadIdx.x;
    int ec0 = blockIdx.y * 80;
    __shared__ __align__(8) float ws[KW][80];  // [kp][j] -> (j,j+1) adjacent
    for (int idx = threadIdx.x; idx < KW * 80; idx += 256) {
        int kp = idx / 80, j = idx - kp * 80;
        int ec = ec0 + j, e = ec >> 7, c = ec & 127;
        float v;
        if (kp < P3) v = wmax[(e * P3 + kp) * C_SZ + c];
        else if (kp < P3 + P2) v = w2[(e * P2 + (kp - P3)) * C_SZ + c];
        else v = w1[e * C_SZ + c];
        ws[kp][j] = v;
    }
    __syncthreads();

    unsigned long long a2[KW];
#pragma unroll
    for (int kp = 0; kp < KW; kp++) {
        float a = g_AbigT[kp * GSZ + o];
        a2[kp] = pack2(a, a);
    }
    for (int j = 0; j < 80; j += 2) {
        unsigned long long acc2 = 0ull;
#pragma unroll
        for (int kp = 0; kp < KW; kp++)
            acc2 = fma2(a2[kp], *(const unsigned long long*)&ws[kp][j], acc2);
        float g0, g1;
        unpack2(g0, g1, acc2);
        size_t ecA = (size_t)(ec0 + j), ecB = ecA + 1;
        __nv_bfloat16 h0 = __float2bfloat16(g0);
        __nv_bfloat16 h1 = __float2bfloat16(g1);
        g_Ghi[ecA * GSZ + o] = h0;
        g_Glo[ecA * GSZ + o] = __float2bfloat16(g0 - __bfloat162float(h0));
        g_Ghi[ecB * GSZ + o] = h1;
        g_Glo[ecB * GSZ + o] = __float2bfloat16(g1 - __bfloat162float(h1));
    }
}

// ---------------------------------------------------------------------------
// Kernel C: per (e,c) CTA, 192 threads (6 warps). A fragments (hi+lo) hoisted
// into REGISTERS once per CTA (tile-invariant); per tile only B (z) comes from
// smem (40 LDS.32 vs 120). Three independent MMA accumulator chains (hh/hl/lh)
// break the 30-deep RAW chain into 3x10.
// ---------------------------------------------------------------------------
#define MMA_BF16(C0, C1, C2, C3, A0, A1, A2, A3, B0, B1)                    \
    asm volatile(                                                           \
        "mma.sync.aligned.m16n8k16.row.col.f32.bf16.bf16.f32 "              \
        "{%0,%1,%2,%3}, {%4,%5,%6,%7}, {%8,%9}, {%0,%1,%2,%3};"             \
        : "+f"(C0), "+f"(C1), "+f"(C2), "+f"(C3)                            \
        : "r"(A0), "r"(A1), "r"(A2), "r"(A3), "r"(B0), "r"(B1))

// truncation split: hi = top-16-bits (exact), lo = RN-bf16 of remainder
static __device__ __forceinline__ uint32_t tsplit(float z0, float z1, uint32_t& lo) {
    uint32_t u0 = __float_as_uint(z0), u1 = __float_as_uint(z1);
    float l0 = z0 - __uint_as_float(u0 & 0xFFFF0000u);
    float l1 = z1 - __uint_as_float(u1 & 0xFFFF0000u);
    uint32_t hi;
    asm("prmt.b32 %0, %1, %2, 0x7632;" : "=r"(hi) : "r"(u0), "r"(u1));
    asm("cvt.rn.bf16x2.f32 %0, %1, %2;" : "=r"(lo) : "f"(l1), "f"(l0));
    return hi;
}

__global__ void __launch_bounds__(192, 2) contract_kernel(
    const float* __restrict__ x, float* __restrict__ out) {
    int c = blockIdx.x, e = blockIdx.y;
    int ec = e * C_SZ + c;
    int t = threadIdx.x;
    int warp = t >> 5, lane = t & 31;
    int mi = warp >> 1, ni = warp & 1;
    int r = lane >> 2, q = lane & 3;

    __shared__ uint32_t Zh[NT * LDA], Zl[NT * LDA];
    __shared__ float xs[NT][ELL];
    __shared__ int border[NT];
    __shared__ unsigned char vlut[KSYM], ilut[KSYM];

    if (t < KSYM) {
        int kk = t, v = 0;
        while (kk >= ELL - v) { kk -= ELL - v; v++; }
        vlut[t] = (unsigned char)v;
        ilut[t] = (unsigned char)(v + kk);
    }

    // Hoist A fragments (hi+lo) into registers: tile-invariant per CTA.
    uint32_t ahr[10][4], alr[10][4];
    {
        const uint32_t* gh = (const uint32_t*)g_Ghi + (size_t)ec * (GSZ / 2);
        const uint32_t* gl = (const uint32_t*)g_Glo + (size_t)ec * (GSZ / 2);
        int row0 = (mi * 16 + r) * KPAIR;
        int row1 = row0 + 8 * KPAIR;
#pragma unroll
        for (int kt = 0; kt < 10; kt++) {
            int kb = kt * 8 + q;
            ahr[kt][0] = gh[row0 + kb];
            ahr[kt][1] = gh[row1 + kb];
            ahr[kt][2] = gh[row0 + kb + 4];
            ahr[kt][3] = gh[row1 + kb + 4];
            alr[kt][0] = gl[row0 + kb];
            alr[kt][1] = gl[row1 + kb];
            alr[kt][2] = gl[row0 + kb + 4];
            alr[kt][3] = gl[row1 + kb + 4];
        }
    }

    int b0 = g_bstart[e], b1 = g_bstart[e + 1];
    for (int tb = b0; tb < b1; tb += NT) {
        int nb = min(NT, b1 - tb);
        if (t < 128) {
            int slot = t >> 3, ii = (t & 7) * 2;
            if (slot < nb) {
                int bidx = g_order[tb + slot];
                if (ii == 0) border[slot] = bidx;
                float2 xv = *(const float2*)&x[((size_t)bidx * C_SZ + c) * ELL + ii];
                xs[slot][ii] = xv.x;
                xs[slot][ii + 1] = xv.y;
            } else {
                xs[slot][ii] = 0.f;
                xs[slot][ii + 1] = 0.f;
            }
        }
        __syncthreads();

        // z build: 16 b's x 80 bf16-pairs (truncation split)
        for (int s = t; s < NT * KPAIR; s += 192) {
            int n = s / KPAIR, kk = s - n * KPAIR;
            const float* xr = xs[n];
            float zz[2];
#pragma unroll
            for (int u = 0; u < 2; u++) {
                int k = 2 * kk + u;
                float zv;
                if (k < KSYM) zv = xr[vlut[k]] * xr[ilut[k]];
                else if (k < KSYM + ELL) zv = xr[k - KSYM];
                else zv = (k == KSYM + ELL) ? 1.f : 0.f;
                zz[u] = zv;
            }
            uint32_t lo;
            uint32_t hi = tsplit(zz[0], zz[1], lo);
            Zh[n * LDA + kk] = hi;
            Zl[n * LDA + kk] = lo;
        }
        __syncthreads();

        // GEMM: 3 independent accumulator chains (hh, hl, lh)
        float h0 = 0.f, h1 = 0.f, h2 = 0.f, h3 = 0.f;
        float m0 = 0.f, m1 = 0.f, m2 = 0.f, m3 = 0.f;
        float l0 = 0.f, l1 = 0.f, l2 = 0.f, l3 = 0.f;
        const uint32_t* Bbh = Zh + (ni * 8 + r) * LDA + q;
        const uint32_t* Bbl = Zl + (ni * 8 + r) * LDA + q;
#pragma unroll
        for (int kt = 0; kt < 10; kt++) {
            int ko = kt * 8;
            uint32_t bh0 = Bbh[ko], bh1 = Bbh[ko + 4];
            uint32_t bl0 = Bbl[ko], bl1 = Bbl[ko + 4];
            MMA_BF16(h0, h1, h2, h3, ahr[kt][0], ahr[kt][1], ahr[kt][2], ahr[kt][3], bh0, bh1);
            MMA_BF16(m0, m1, m2, m3, ahr[kt][0], ahr[kt][1], ahr[kt][2], ahr[kt][3], bl0, bl1);
            MMA_BF16(l0, l1, l2, l3, alr[kt][0], alr[kt][1], alr[kt][2], alr[kt][3], bh0, bh1);
        }
        float c0 = h0 + m0 + l0;
        float c1 = h1 + m1 + l1;
        float c2 = h2 + m2 + l2;
        float c3 = h3 + m3 + l3;

        // epilogue: out[w,b] = sum_xx xs[b][xx] * Q[xx, b]
        int bc0 = ni * 8 + 2 * q, bc1 = bc0 + 1;
        float p0 = c0 * xs[bc0][r] + c2 * xs[bc0][r + 8];
        float p1 = c1 * xs[bc1][r] + c3 * xs[bc1][r + 8];
#pragma unroll
        for (int off = 4; off <= 16; off <<= 1) {
            p0 += __shfl_xor_sync(0xffffffffu, p0, off);
            p1 += __shfl_xor_sync(0xffffffffu, p1, off);
        }
        if (lane < 4) {
            if (bc0 < nb) out[(size_t)border[bc0] * OUT_STRIDE + c * EQ + mi] = p0;
            if (bc1 < nb) out[(size_t)border[bc1] * OUT_STRIDE + c * EQ + mi] = p1;
        }
        __syncthreads();
    }
}

// ---------------------------------------------------------------------------
extern "C" void kernel_launch(void* const* d_in, const int* in_sizes, int n_in,
                              void* d_out, int out_size) {
    const float* x    = (const float*)d_in[0];
    const float* y    = (const float*)d_in[1];
    const float* U3   = (const float*)d_in[2];
    const float* U2   = (const float*)d_in[3];
    const float* U1   = (const float*)d_in[4];
    const float* wmax = (const float*)d_in[5];
    const float* w2   = (const float*)d_in[6];
    const float* w1   = (const float*)d_in[7];
    float* out = (float*)d_out;

    bucket_kernel<<<1, B_SZ>>>(y);
    build_abig_kernel<<<30, 256>>>(U3, U2, U1);
    build_g_kernel<<<dim3(30, 16), 256>>>(wmax, w2, w1);
    contract_kernel<<<dim3(C_SZ, E_SZ), 192>>>(x, out);
}

// round 12
// speedup vs baseline: 1.1557x; 1.1557x over previous
#include <cuda_runtime.h>
#include <cuda_bf16.h>
#include <cstdint>

#define B_SZ 1024
#define C_SZ 128
#define ELL 16
#define EQ 3
#define E_SZ 10
#define P3 23
#define P2 5
#define OUT_STRIDE 384
#define MROWS 48           // (w,xx) rows, m = w*16 + xx
#define KTOT 160           // 128 quad + 8 cross + 16 lin + 1 const + 7 pad
#define KPAIR 80
#define KW 29              // 23 + 5 + 1 weight slots
#define NT 32              // b-tile
#define GSZ (MROWS * KTOT) // 7680
#define LDA 84             // A smem pair-stride (conflict-free)
#define LDZ 164            // Z smem u32 row stride (82 pairs x 2 interleaved)
#define XSW 17             // xs row stride (floats)

__device__ int g_order[B_SZ];
__device__ int g_bstart[E_SZ + 1];
__device__ __align__(16) float g_AbigT[KW * GSZ];                 // [kp][o]
__device__ __align__(16) __nv_bfloat16 g_Ghi[E_SZ * C_SZ * GSZ];
__device__ __align__(16) __nv_bfloat16 g_Glo[E_SZ * C_SZ * GSZ];

// ---- packed f32x2 helpers ----
static __device__ __forceinline__ unsigned long long pack2(float lo, float hi) {
    unsigned long long r;
    asm("mov.b64 %0, {%1, %2};" : "=l"(r) : "f"(lo), "f"(hi));
    return r;
}
static __device__ __forceinline__ void unpack2(float& lo, float& hi, unsigned long long v) {
    asm("mov.b64 {%0, %1}, %2;" : "=f"(lo), "=f"(hi) : "l"(v));
}
static __device__ __forceinline__ unsigned long long fma2(unsigned long long a,
                                                          unsigned long long b,
                                                          unsigned long long c) {
    unsigned long long d;
    asm("fma.rn.f32x2 %0, %1, %2, %3;" : "=l"(d) : "l"(a), "l"(b), "l"(c));
    return d;
}

// ---------------------------------------------------------------------------
// Kernel A: bucket batch indices by element (y is exact one-hot).
// ---------------------------------------------------------------------------
__global__ void bucket_kernel(const float* __restrict__ y) {
    __shared__ int cnt[E_SZ];
    __shared__ int pfx[E_SZ + 1];
    int b = threadIdx.x;
    if (b < E_SZ) cnt[b] = 0;
    __syncthreads();
    int e = 0;
#pragma unroll
    for (int j = 1; j < E_SZ; j++)
        if (y[b * E_SZ + j] > 0.5f) e = j;
    int idx = atomicAdd(&cnt[e], 1);
    __syncthreads();
    if (b == 0) {
        int s = 0;
        for (int j = 0; j < E_SZ; j++) { pfx[j] = s; s += cnt[j]; }
        pfx[E_SZ] = s;
    }
    __syncthreads();
    g_order[pfx[e] + idx] = b;
    if (b <= E_SZ) g_bstart[b] = pfx[b];
}

// ---------------------------------------------------------------------------
// Kernel B1: AbigT[kp][m*160+k] with (d,v) enumeration:
//   k < 128 : d=k>>4, v=k&15, i=(v+d)&15. d==0 -> U3[m,v,v]; else U3[m,v,i]+U3[m,i,v]
//   128..135: v=k-128, i=v+8 -> U3[m,v,i]+U3[m,i,v]
//   136..151: U2[m, k-136, *]  (slots 23..27)
//   k == 152: U1[m]            (slot 28)
// ---------------------------------------------------------------------------
__global__ void build_abig_kernel(const float* __restrict__ U3,
                                  const float* __restrict__ U2,
                                  const float* __restrict__ U1) {
    int o = blockIdx.x * 256 + threadIdx.x;
    if (o >= GSZ) return;
    int m = o / KTOT, k = o % KTOT;
    float vals[KW];
#pragma unroll
    for (int j = 0; j < KW; j++) vals[j] = 0.f;
    int v = -1, i = -1;
    if (k < 128) {
        int d = k >> 4;
        v = k & 15;
        i = (v + d) & 15;
        if (d == 0) i = -2;  // diag marker
    } else if (k < 136) {
        v = k - 128;
        i = v + 8;
    }
    if (v >= 0) {
        if (i == -2) {  // diagonal
            const float* p1 = U3 + ((size_t)(m * ELL + v) * ELL + v) * P3;
#pragma unroll
            for (int kp = 0; kp < P3; kp++) vals[kp] = p1[kp];
        } else {
            const float* p1 = U3 + ((size_t)(m * ELL + v) * ELL + i) * P3;
            const float* p2 = U3 + ((size_t)(m * ELL + i) * ELL + v) * P3;
#pragma unroll
            for (int kp = 0; kp < P3; kp++) vals[kp] = p1[kp] + p2[kp];
        }
    } else if (k >= 136 && k < 152) {
        int vv = k - 136;
#pragma unroll
        for (int k2 = 0; k2 < P2; k2++)
            vals[P3 + k2] = U2[(m * ELL + vv) * P2 + k2];
    } else if (k == 152) {
        vals[P3 + P2] = U1[m];
    }
#pragma unroll
    for (int j = 0; j < KW; j++)
        g_AbigT[j * GSZ + o] = vals[j];
}

// ---------------------------------------------------------------------------
// Kernel B2: G[ec, o] = sum_kp AbigT[kp, o] * W[ec, kp]; bf16 hi/lo split.
// ---------------------------------------------------------------------------
__global__ void __launch_bounds__(256) build_g_kernel(
    const float* __restrict__ wmax, const float* __restrict__ w2,
    const float* __restrict__ w1) {
    int o = blockIdx.x * 256 + threadIdx.x;
    int ec0 = blockIdx.y * 80;
    __shared__ __align__(8) float ws[KW][80];
    for (int idx = threadIdx.x; idx < KW * 80; idx += 256) {
        int kp = idx / 80, j = idx - kp * 80;
        int ec = ec0 + j, e = ec >> 7, c = ec & 127;
        float v;
        if (kp < P3) v = wmax[(e * P3 + kp) * C_SZ + c];
        else if (kp < P3 + P2) v = w2[(e * P2 + (kp - P3)) * C_SZ + c];
        else v = w1[e * C_SZ + c];
        ws[kp][j] = v;
    }
    __syncthreads();

    unsigned long long a2[KW];
#pragma unroll
    for (int kp = 0; kp < KW; kp++) {
        float a = g_AbigT[kp * GSZ + o];
        a2[kp] = pack2(a, a);
    }
    for (int j = 0; j < 80; j += 2) {
        unsigned long long acc2 = 0ull;
#pragma unroll
        for (int kp = 0; kp < KW; kp++)
            acc2 = fma2(a2[kp], *(const unsigned long long*)&ws[kp][j], acc2);
        float g0, g1;
        unpack2(g0, g1, acc2);
        size_t ecA = (size_t)(ec0 + j), ecB = ecA + 1;
        __nv_bfloat16 h0 = __float2bfloat16(g0);
        __nv_bfloat16 h1 = __float2bfloat16(g1);
        g_Ghi[ecA * GSZ + o] = h0;
        g_Glo[ecA * GSZ + o] = __float2bfloat16(g0 - __bfloat162float(h0));
        g_Ghi[ecB * GSZ + o] = h1;
        g_Glo[ecB * GSZ + o] = __float2bfloat16(g1 - __bfloat162float(h1));
    }
}

// ---------------------------------------------------------------------------
// Kernel C: per (e,c) CTA, 192 threads (6 warps), NT=32 b-tile.
// A (bf16 hi/lo) in smem; warp (mi, ni) computes m-tile mi for TWO n-frags
// (cols ni*8 and 16+ni*8) reusing the same A fragments (A traffic per b
// halves). Z stored interleaved (hi,lo) -> STS.64 writes / LDS.64 reads.
// 6 independent MMA accumulator chains. z-build is warp-uniform, shift-only
// indexing (no divides, no LUTs).
// ---------------------------------------------------------------------------
#define MMA_BF16(CC, A0, A1, A2, A3, B0, B1)                                \
    asm volatile(                                                           \
        "mma.sync.aligned.m16n8k16.row.col.f32.bf16.bf16.f32 "              \
        "{%0,%1,%2,%3}, {%4,%5,%6,%7}, {%8,%9}, {%0,%1,%2,%3};"             \
        : "+f"(CC[0]), "+f"(CC[1]), "+f"(CC[2]), "+f"(CC[3])                \
        : "r"(A0), "r"(A1), "r"(A2), "r"(A3), "r"(B0), "r"(B1))

// truncation split: hi = top-16-bits (exact), lo = RN-bf16 of remainder
static __device__ __forceinline__ uint32_t tsplit(float z0, float z1, uint32_t& lo) {
    uint32_t u0 = __float_as_uint(z0), u1 = __float_as_uint(z1);
    float l0 = z0 - __uint_as_float(u0 & 0xFFFF0000u);
    float l1 = z1 - __uint_as_float(u1 & 0xFFFF0000u);
    uint32_t hi;
    asm("prmt.b32 %0, %1, %2, 0x7632;" : "=r"(hi) : "r"(u0), "r"(u1));
    asm("cvt.rn.bf16x2.f32 %0, %1, %2;" : "=r"(lo) : "f"(l1), "f"(l0));
    return hi;
}

__global__ void __launch_bounds__(192, 4) contract_kernel(
    const float* __restrict__ x, float* __restrict__ out) {
    int c = blockIdx.x, e = blockIdx.y;
    int ec = e * C_SZ + c;
    int t = threadIdx.x;
    int warp = t >> 5, lane = t & 31;
    int mi = warp >> 1, ni = warp & 1;
    int r = lane >> 2, q = lane & 3;

    __shared__ __align__(16) uint32_t Ah[MROWS * LDA], Al[MROWS * LDA];
    __shared__ __align__(16) uint32_t Z[NT * LDZ];     // [n][pair*2 + {hi,lo}]
    __shared__ float xs[NT * XSW];
    __shared__ int border[NT];

    // Load A (hi+lo) into smem, once per CTA.
    {
        const uint32_t* gh = (const uint32_t*)g_Ghi + (size_t)ec * (GSZ / 2);
        const uint32_t* gl = (const uint32_t*)g_Glo + (size_t)ec * (GSZ / 2);
        for (int p = t; p < MROWS * KPAIR; p += 192) {
            int m = p / KPAIR, kk = p - m * KPAIR;
            Ah[m * LDA + kk] = gh[p];
            Al[m * LDA + kk] = gl[p];
        }
    }

    int b0 = g_bstart[e], b1 = g_bstart[e + 1];
    for (int tb = b0; tb < b1; tb += NT) {
        int nb = min(NT, b1 - tb);
        // x load: 32 slots x 16 elems = 512, 3 passes of 192
        for (int idx = t; idx < NT * ELL; idx += 192) {
            int slot = idx >> 4, ii = idx & 15;
            float vv = 0.f;
            if (slot < nb) {
                int bidx = g_order[tb + slot];
                if (ii == 0) border[slot] = bidx;
                vv = x[((size_t)bidx * C_SZ + c) * ELL + ii];
            }
            xs[slot * XSW + ii] = vv;
        }
        __syncthreads();

        // z build: slot n = lane, pair kk = warp..80 step 6 (warp-uniform kk)
        {
            const float* xr = xs + lane * XSW;
            uint32_t* zrow = Z + lane * LDZ;
            for (int kk = warp; kk < KPAIR; kk += 6) {
                float z0, z1;
                if (kk < 64) {
                    int d = kk >> 3;
                    int v0 = (kk & 7) * 2;
                    int i0 = (v0 + d) & 15;
                    int i1 = (v0 + 1 + d) & 15;
                    z0 = xr[v0] * xr[i0];
                    z1 = xr[v0 + 1] * xr[i1];
                } else if (kk < 68) {
                    int v0 = (kk - 64) * 2;
                    z0 = xr[v0] * xr[v0 + 8];
                    z1 = xr[v0 + 1] * xr[v0 + 9];
                } else if (kk < 76) {
                    int base = (kk - 68) * 2;
                    z0 = xr[base];
                    z1 = xr[base + 1];
                } else if (kk == 76) {
                    z0 = 1.f; z1 = 0.f;
                } else {
                    z0 = 0.f; z1 = 0.f;
                }
                uint32_t lo;
                uint32_t hi = tsplit(z0, z1, lo);
                *(uint2*)&zrow[kk * 2] = make_uint2(hi, lo);
            }
        }
        __syncthreads();

        // GEMM: 6 independent chains (hh, hl, lh) x (frag0, frag1)
        float acc[6][4];
#pragma unroll
        for (int s = 0; s < 6; s++)
#pragma unroll
            for (int j = 0; j < 4; j++) acc[s][j] = 0.f;

        const uint32_t* Ahb = Ah + (mi * 16 + r) * LDA + q;
        const uint32_t* Alb = Al + (mi * 16 + r) * LDA + q;
        const uint32_t* Zb0 = Z + (ni * 8 + r) * LDZ;
        const uint32_t* Zb1 = Z + (16 + ni * 8 + r) * LDZ;
#pragma unroll
        for (int kt = 0; kt < 10; kt++) {
            int ko = kt * 8;
            uint32_t ah0 = Ahb[ko], ah1 = Ahb[ko + 8 * LDA];
            uint32_t ah2 = Ahb[ko + 4], ah3 = Ahb[ko + 8 * LDA + 4];
            uint32_t al0 = Alb[ko], al1 = Alb[ko + 8 * LDA];
            uint32_t al2 = Alb[ko + 4], al3 = Alb[ko + 8 * LDA + 4];
            uint2 b00 = *(const uint2*)&Zb0[(ko + q) * 2];
            uint2 b01 = *(const uint2*)&Zb0[(ko + q + 4) * 2];
            uint2 b10 = *(const uint2*)&Zb1[(ko + q) * 2];
            uint2 b11 = *(const uint2*)&Zb1[(ko + q + 4) * 2];
            MMA_BF16(acc[0], ah0, ah1, ah2, ah3, b00.x, b01.x);  // hh f0
            MMA_BF16(acc[1], ah0, ah1, ah2, ah3, b00.y, b01.y);  // hl f0
            MMA_BF16(acc[2], al0, al1, al2, al3, b00.x, b01.x);  // lh f0
            MMA_BF16(acc[3], ah0, ah1, ah2, ah3, b10.x, b11.x);  // hh f1
            MMA_BF16(acc[4], ah0, ah1, ah2, ah3, b10.y, b11.y);  // hl f1
            MMA_BF16(acc[5], al0, al1, al2, al3, b10.x, b11.x);  // lh f1
        }

        // epilogue per fragment: out[w,b] = sum_xx xs[b][xx] * Q[xx, b]
#pragma unroll
        for (int f = 0; f < 2; f++) {
            float c0 = acc[3 * f][0] + acc[3 * f + 1][0] + acc[3 * f + 2][0];
            float c1 = acc[3 * f][1] + acc[3 * f + 1][1] + acc[3 * f + 2][1];
            float c2 = acc[3 * f][2] + acc[3 * f + 1][2] + acc[3 * f + 2][2];
            float c3 = acc[3 * f][3] + acc[3 * f + 1][3] + acc[3 * f + 2][3];
            int bc0 = f * 16 + ni * 8 + 2 * q;
            int bc1 = bc0 + 1;
            float p0 = c0 * xs[bc0 * XSW + r] + c2 * xs[bc0 * XSW + r + 8];
            float p1 = c1 * xs[bc1 * XSW + r] + c3 * xs[bc1 * XSW + r + 8];
#pragma unroll
            for (int off = 4; off <= 16; off <<= 1) {
                p0 += __shfl_xor_sync(0xffffffffu, p0, off);
                p1 += __shfl_xor_sync(0xffffffffu, p1, off);
            }
            if (lane < 4) {
                if (bc0 < nb) out[(size_t)border[bc0] * OUT_STRIDE + c * EQ + mi] = p0;
                if (bc1 < nb) out[(size_t)border[bc1] * OUT_STRIDE + c * EQ + mi] = p1;
            }
        }
        __syncthreads();
    }
}

// ---------------------------------------------------------------------------
extern "C" void kernel_launch(void* const* d_in, const int* in_sizes, int n_in,
                              void* d_out, int out_size) {
    const float* x    = (const float*)d_in[0];
    const float* y    = (const float*)d_in[1];
    const float* U3   = (const float*)d_in[2];
    const float* U2   = (const float*)d_in[3];
    const float* U1   = (const float*)d_in[4];
    const float* wmax = (const float*)d_in[5];
    const float* w2   = (const float*)d_in[6];
    const float* w1   = (const float*)d_in[7];
    float* out = (float*)d_out;

    bucket_kernel<<<1, B_SZ>>>(y);
    build_abig_kernel<<<30, 256>>>(U3, U2, U1);
    build_g_kernel<<<dim3(30, 16), 256>>>(wmax, w2, w1);
    contract_kernel<<<dim3(C_SZ, E_SZ), 192>>>(x, out);
}